// round 1
// baseline (speedup 1.0000x reference)
#include <cuda_runtime.h>

// ---------------------------------------------------------------------------
// Model dims
// ---------------------------------------------------------------------------
constexpr int NL  = 6;
constexpr int NH  = 16;
constexpr int DM  = 1024;
constexpr int DH  = 64;
constexpr int DFF = 4096;
constexpr int NV  = 32000;
constexpr int NB  = 2;
constexpr int NS  = 1024;
constexpr int NT  = NB * NS;   // 2048 tokens

// ---------------------------------------------------------------------------
// Scratch (device globals — no runtime allocation allowed)
// ---------------------------------------------------------------------------
__device__ float g_x  [NT * DM];          // current activations
__device__ float g_res[NT * DM];          // pre-layernorm sum
__device__ float g_q  [NT * DM];
__device__ float g_k  [NT * DM];
__device__ float g_v  [NT * DM];
__device__ float g_o  [NT * DM];          // concat heads attn output
__device__ float g_ffn[NT * DFF];
__device__ float g_sc [(long)NB * NH * NS * NS]; // 128 MB attention scores

// ---------------------------------------------------------------------------
// Generic batched GEMM: C = A@B (+bias) (+Res) (optional relu)
// A[M,K] lda, B[K,N] ldb (row-major), C[M,N] ldc.
// blockIdx.z decomposed as zb = z/zdiv, zh = z%zdiv with per-matrix strides.
// All launch shapes divide tiles exactly (asserted by construction).
// ---------------------------------------------------------------------------
template<int BM, int BN, int BK, int TM, int TN>
__global__ void __launch_bounds__(256)
gemm_kernel(const float* __restrict__ A, const float* __restrict__ B,
            const float* __restrict__ bias, const float* __restrict__ Res,
            float* __restrict__ C,
            int M, int N, int K, int lda, int ldb, int ldc,
            int zdiv, long sAb, long sAh, long sBb, long sBh,
            long sCb, long sCh, int relu)
{
    constexpr int THREADS = (BM / TM) * (BN / TN);
    static_assert(THREADS == 256, "block size");

    const int zb = blockIdx.z / zdiv;
    const int zh = blockIdx.z % zdiv;
    A += zb * sAb + zh * sAh;
    B += zb * sBb + zh * sBh;
    const long coff = zb * sCb + zh * sCh;
    C += coff;
    if (Res) Res += coff;

    __shared__ float As[BK][BM];
    __shared__ float Bs[BK][BN];

    const int m0 = blockIdx.x * BM;
    const int n0 = blockIdx.y * BN;

    const int tid = threadIdx.x;
    const int tm0 = (tid / (BN / TN)) * TM;
    const int tn0 = (tid % (BN / TN)) * TN;

    float acc[TM][TN] = {};

    constexpr int LA = BM * BK / THREADS;
    constexpr int LB = BK * BN / THREADS;

    for (int k0 = 0; k0 < K; k0 += BK) {
        #pragma unroll
        for (int r = 0; r < LA; r++) {
            int i = tid + r * THREADS;
            int m = i / BK, kk = i % BK;
            As[kk][m] = A[(long)(m0 + m) * lda + (k0 + kk)];
        }
        #pragma unroll
        for (int r = 0; r < LB; r++) {
            int i = tid + r * THREADS;
            int kk = i / BN, n = i % BN;
            Bs[kk][n] = B[(long)(k0 + kk) * ldb + (n0 + n)];
        }
        __syncthreads();

        #pragma unroll
        for (int kk = 0; kk < BK; kk++) {
            float ra[TM], rb[TN];
            #pragma unroll
            for (int i = 0; i < TM; i++) ra[i] = As[kk][tm0 + i];
            #pragma unroll
            for (int j = 0; j < TN; j++) rb[j] = Bs[kk][tn0 + j];
            #pragma unroll
            for (int i = 0; i < TM; i++)
                #pragma unroll
                for (int j = 0; j < TN; j++)
                    acc[i][j] += ra[i] * rb[j];
        }
        __syncthreads();
    }

    #pragma unroll
    for (int i = 0; i < TM; i++) {
        const int m = m0 + tm0 + i;
        #pragma unroll
        for (int j = 0; j < TN; j++) {
            const int n = n0 + tn0 + j;
            float v = acc[i][j];
            if (bias) v += bias[n];
            if (Res)  v += Res[(long)m * ldc + n];
            if (relu) v = fmaxf(v, 0.0f);
            C[(long)m * ldc + n] = v;
        }
    }
}

// ---------------------------------------------------------------------------
// Attention scores: sc[z, i, j] = (q_i . k_j) / 8 (causal masked to -1e30)
// q,k layout [tok, H*DH]; z = b*NH + h. Block: 64x64 tile, 16x16 threads.
// ---------------------------------------------------------------------------
__global__ void __launch_bounds__(256)
scores_kernel(const float* __restrict__ q, const float* __restrict__ k,
              float* __restrict__ sc)
{
    const int z = blockIdx.z;
    const int b = z >> 4;          // / NH
    const int h = z & 15;          // % NH
    const int it = blockIdx.y, jt = blockIdx.x;
    const int i0 = it * 64, j0 = jt * 64;
    const long base = (long)z * NS * NS;
    const int tx = threadIdx.x & 15, ty = threadIdx.x >> 4;

    if (jt > it) {  // fully masked tile
        #pragma unroll
        for (int ii = 0; ii < 4; ii++)
            #pragma unroll
            for (int jj = 0; jj < 4; jj++)
                sc[base + (long)(i0 + ty * 4 + ii) * NS + (j0 + tx * 4 + jj)] = -1e30f;
        return;
    }

    __shared__ float qs[64][65];
    __shared__ float ks[64][65];
    const int tid = threadIdx.x;
    #pragma unroll
    for (int p = 0; p < 16; p++) {
        int idx = tid + p * 256;
        int row = idx >> 6, col = idx & 63;
        qs[row][col] = q[(long)(b * NS + i0 + row) * DM + h * DH + col];
        ks[row][col] = k[(long)(b * NS + j0 + row) * DM + h * DH + col];
    }
    __syncthreads();

    float acc[4][4] = {};
    #pragma unroll
    for (int kk = 0; kk < 64; kk++) {
        float ra[4], rb[4];
        #pragma unroll
        for (int i = 0; i < 4; i++) ra[i] = qs[ty * 4 + i][kk];
        #pragma unroll
        for (int j = 0; j < 4; j++) rb[j] = ks[tx * 4 + j][kk];
        #pragma unroll
        for (int i = 0; i < 4; i++)
            #pragma unroll
            for (int j = 0; j < 4; j++)
                acc[i][j] += ra[i] * rb[j];
    }

    #pragma unroll
    for (int ii = 0; ii < 4; ii++) {
        const int i = i0 + ty * 4 + ii;
        #pragma unroll
        for (int jj = 0; jj < 4; jj++) {
            const int j = j0 + tx * 4 + jj;
            sc[base + (long)i * NS + j] = (j <= i) ? acc[ii][jj] * 0.125f : -1e30f;
        }
    }
}

// ---------------------------------------------------------------------------
// Row softmax over 1024 cols; one block per row.
// ---------------------------------------------------------------------------
__global__ void __launch_bounds__(256)
softmax_kernel(float* __restrict__ sc)
{
    float* p = sc + (long)blockIdx.x * NS;
    const int tid = threadIdx.x;
    __shared__ float red[256];

    float vals[4];
    float lm = -1e30f;
    #pragma unroll
    for (int i = 0; i < 4; i++) { vals[i] = p[tid + i * 256]; lm = fmaxf(lm, vals[i]); }
    red[tid] = lm; __syncthreads();
    for (int s = 128; s > 0; s >>= 1) {
        if (tid < s) red[tid] = fmaxf(red[tid], red[tid + s]);
        __syncthreads();
    }
    const float mx = red[0]; __syncthreads();

    float ls = 0.0f;
    #pragma unroll
    for (int i = 0; i < 4; i++) { vals[i] = expf(vals[i] - mx); ls += vals[i]; }
    red[tid] = ls; __syncthreads();
    for (int s = 128; s > 0; s >>= 1) {
        if (tid < s) red[tid] += red[tid + s];
        __syncthreads();
    }
    const float inv = 1.0f / red[0];
    #pragma unroll
    for (int i = 0; i < 4; i++) p[tid + i * 256] = vals[i] * inv;
}

// ---------------------------------------------------------------------------
// LayerNorm (torch-style: unbiased std, divide by (std + eps))
// one block per token row.
// ---------------------------------------------------------------------------
__global__ void __launch_bounds__(256)
ln_kernel(const float* __restrict__ in, const float* __restrict__ g,
          const float* __restrict__ b, float* __restrict__ out)
{
    const float* p = in + (long)blockIdx.x * DM;
    float* po = out + (long)blockIdx.x * DM;
    const int tid = threadIdx.x;
    __shared__ float red[256];

    float vals[4];
    float s = 0.0f;
    #pragma unroll
    for (int i = 0; i < 4; i++) { vals[i] = p[tid + i * 256]; s += vals[i]; }
    red[tid] = s; __syncthreads();
    for (int st = 128; st > 0; st >>= 1) {
        if (tid < st) red[tid] += red[tid + st];
        __syncthreads();
    }
    const float mean = red[0] * (1.0f / DM); __syncthreads();

    float sq = 0.0f;
    #pragma unroll
    for (int i = 0; i < 4; i++) { float d = vals[i] - mean; sq += d * d; }
    red[tid] = sq; __syncthreads();
    for (int st = 128; st > 0; st >>= 1) {
        if (tid < st) red[tid] += red[tid + st];
        __syncthreads();
    }
    const float sd = sqrtf(red[0] / (DM - 1));
    const float inv = 1.0f / (sd + 1e-6f);
    #pragma unroll
    for (int i = 0; i < 4; i++) {
        int d = tid + i * 256;
        po[d] = g[d] * (vals[i] - mean) * inv + b[d];
    }
}

// ---------------------------------------------------------------------------
// Embedding + sinusoidal positional encoding: x = emb[tok]*sqrt(DM) + PE
// ---------------------------------------------------------------------------
__global__ void __launch_bounds__(256)
embed_kernel(const int* __restrict__ tokens, const float* __restrict__ emb,
             float* __restrict__ x)
{
    const int t = blockIdx.x;           // token 0..NT-1
    const int s = t & (NS - 1);         // position within sequence
    const int tok = tokens[t];
    const float* e = emb + (long)tok * DM;
    float* xo = x + (long)t * DM;
    const float nlog = -9.210340371976184f / (float)DM;  // -ln(10000)/DM
    for (int d = threadIdx.x; d < DM; d += 256) {
        int i2 = d & ~1;
        float freq = expf((float)i2 * nlog);
        float ang = (float)s * freq;
        float pe = (d & 1) ? cosf(ang) : sinf(ang);
        xo[d] = e[d] * 32.0f + pe;      // sqrt(1024) = 32
    }
}

// ---------------------------------------------------------------------------
// Host orchestration
// ---------------------------------------------------------------------------
extern "C" void kernel_launch(void* const* d_in, const int* in_sizes, int n_in,
                              void* d_out, int out_size)
{
    const int*   tokens = (const int*)  d_in[0];
    const float* emb    = (const float*)d_in[1];
    const float* Wq     = (const float*)d_in[2];
    const float* Wk     = (const float*)d_in[3];
    const float* Wv     = (const float*)d_in[4];
    const float* Wo     = (const float*)d_in[5];
    const float* bo     = (const float*)d_in[6];
    const float* ln1g   = (const float*)d_in[7];
    const float* ln1b   = (const float*)d_in[8];
    const float* W1     = (const float*)d_in[9];
    const float* b1     = (const float*)d_in[10];
    const float* W2     = (const float*)d_in[11];
    const float* b2     = (const float*)d_in[12];
    const float* ln2g   = (const float*)d_in[13];
    const float* ln2b   = (const float*)d_in[14];
    const float* Wout   = (const float*)d_in[15];
    const float* bout   = (const float*)d_in[16];
    float* out = (float*)d_out;

    float *x, *res, *q, *k, *v, *o, *ffn, *sc;
    cudaGetSymbolAddress((void**)&x,   g_x);
    cudaGetSymbolAddress((void**)&res, g_res);
    cudaGetSymbolAddress((void**)&q,   g_q);
    cudaGetSymbolAddress((void**)&k,   g_k);
    cudaGetSymbolAddress((void**)&v,   g_v);
    cudaGetSymbolAddress((void**)&o,   g_o);
    cudaGetSymbolAddress((void**)&ffn, g_ffn);
    cudaGetSymbolAddress((void**)&sc,  g_sc);

    embed_kernel<<<NT, 256>>>(tokens, emb, x);

    for (int l = 0; l < NL; l++) {
        const float* Wql = Wq + (long)l * NH * DM * DH;
        const float* Wkl = Wk + (long)l * NH * DM * DH;
        const float* Wvl = Wv + (long)l * NH * DM * DH;
        const float* Wol = Wo + (long)l * DM * DM;
        const float* bol = bo + (long)l * DM;
        const float* W1l = W1 + (long)l * DM * DFF;
        const float* b1l = b1 + (long)l * DFF;
        const float* W2l = W2 + (long)l * DFF * DM;
        const float* b2l = b2 + (long)l * DM;

        // Q/K/V projections: per-head GEMM, N=DH, batched over heads
        dim3 gqkv(NT / 64, 1, NH);
        gemm_kernel<64,64,16,4,4><<<gqkv, 256>>>(x, Wql, nullptr, nullptr, q,
            NT, DH, DM, DM, DH, DM, NH, 0, 0, 0, (long)DM * DH, 0, DH, 0);
        gemm_kernel<64,64,16,4,4><<<gqkv, 256>>>(x, Wkl, nullptr, nullptr, k,
            NT, DH, DM, DM, DH, DM, NH, 0, 0, 0, (long)DM * DH, 0, DH, 0);
        gemm_kernel<64,64,16,4,4><<<gqkv, 256>>>(x, Wvl, nullptr, nullptr, v,
            NT, DH, DM, DM, DH, DM, NH, 0, 0, 0, (long)DM * DH, 0, DH, 0);

        // scores + softmax
        dim3 gsc(NS / 64, NS / 64, NB * NH);
        scores_kernel<<<gsc, 256>>>(q, k, sc);
        softmax_kernel<<<NB * NH * NS, 256>>>(sc);

        // o = att @ v (batched over b,h)
        dim3 gav(NS / 64, 1, NB * NH);
        gemm_kernel<64,64,16,4,4><<<gav, 256>>>(sc, v, nullptr, nullptr, o,
            NS, DH, NS, NS, DM, DM, NH,
            (long)NH * NS * NS, (long)NS * NS,
            (long)NS * DM, DH, (long)NS * DM, DH, 0);

        // O projection + residual
        dim3 gw(NT / 128, DM / 128);
        gemm_kernel<128,128,8,8,8><<<gw, 256>>>(o, Wol, bol, x, res,
            NT, DM, DM, DM, DM, DM, 1, 0, 0, 0, 0, 0, 0, 0);
        ln_kernel<<<NT, 256>>>(res, ln1g + (long)l * DM, ln1b + (long)l * DM, x);

        // FFN
        dim3 g1(NT / 128, DFF / 128);
        gemm_kernel<128,128,8,8,8><<<g1, 256>>>(x, W1l, b1l, nullptr, ffn,
            NT, DFF, DM, DM, DFF, DFF, 1, 0, 0, 0, 0, 0, 0, 1);
        dim3 g2(NT / 128, DM / 128);
        gemm_kernel<128,128,8,8,8><<<g2, 256>>>(ffn, W2l, b2l, x, res,
            NT, DM, DFF, DFF, DM, DM, 1, 0, 0, 0, 0, 0, 0, 0);
        ln_kernel<<<NT, 256>>>(res, ln2g + (long)l * DM, ln2b + (long)l * DM, x);
    }

    // Final vocab projection
    dim3 gf(NT / 128, NV / 128);
    gemm_kernel<128,128,8,8,8><<<gf, 256>>>(x, Wout, bout, nullptr, out,
        NT, NV, DM, DM, NV, NV, 1, 0, 0, 0, 0, 0, 0, 0);
}

// round 2
// speedup vs baseline: 3.6658x; 3.6658x over previous
#include <cuda_runtime.h>
#include <cstdint>

// ---------------------------------------------------------------------------
constexpr int NL  = 6;
constexpr int NH  = 16;
constexpr int DM  = 1024;
constexpr int DH  = 64;
constexpr int DFF = 4096;
constexpr int NV  = 32000;
constexpr int NB  = 2;
constexpr int NS  = 1024;
constexpr int NT  = NB * NS;

// ---------------------------------------------------------------------------
// Scratch (device globals)
// ---------------------------------------------------------------------------
__device__ float g_x  [NT * DM];
__device__ float g_res[NT * DM];
__device__ float g_q  [NT * DM];
__device__ float g_k  [NT * DM];
__device__ float g_v  [NT * DM];
__device__ float g_o  [NT * DM];
__device__ float g_ffn[NT * DFF];
__device__ float g_kt [NB * NH * DH * NS];           // K transposed per head
__device__ float g_sc [(long)NB * NH * NS * NS];     // attention scores

// ---------------------------------------------------------------------------
__device__ __forceinline__ unsigned f2tf(float f) {
    unsigned u;
    asm("cvt.rna.tf32.f32 %0, %1;" : "=r"(u) : "f"(f));
    return u;
}

__device__ __forceinline__ void mma8(float* c, const unsigned* a, unsigned b0, unsigned b1) {
    asm volatile(
        "mma.sync.aligned.m16n8k8.row.col.f32.tf32.tf32.f32 "
        "{%0,%1,%2,%3}, {%4,%5,%6,%7}, {%8,%9}, {%0,%1,%2,%3};"
        : "+f"(c[0]), "+f"(c[1]), "+f"(c[2]), "+f"(c[3])
        : "r"(a[0]), "r"(a[1]), "r"(a[2]), "r"(a[3]), "r"(b0), "r"(b1));
}

// ---------------------------------------------------------------------------
// tf32 tensor-core GEMM.  BM=128, BK=16, BN template (128 or 64).
// 256 threads = 8 warps (4 M x 2 N).  Warp tile 32 x (BN/2).
// flags: 1=bias, 2=residual add, 4=relu, 8=causal(+scale)
// ---------------------------------------------------------------------------
template<int BN>
__global__ void __launch_bounds__(256)
gemm_tc(const float* __restrict__ A, const float* __restrict__ B,
        const float* __restrict__ bias, const float* __restrict__ Res,
        float* __restrict__ C, int K,
        int lda, int ldb, int ldc, int zdiv,
        long sAb, long sAh, long sBb, long sBh, long sCb, long sCh,
        int flags, float scale)
{
    constexpr int BM = 128, BK = 16;
    constexpr int WN = BN / 2;
    constexpr int NTN = WN / 8;
    constexpr int BNP = BN + 8;

    const int zb = blockIdx.z / zdiv, zh = blockIdx.z % zdiv;
    A += zb * sAb + zh * sAh;
    B += zb * sBb + zh * sBh;
    const long coff = (long)zb * sCb + (long)zh * sCh;

    const int m0 = blockIdx.x * BM;
    const int n0 = blockIdx.y * BN;
    const int tid = threadIdx.x;

    const bool causal = (flags & 8) != 0;
    if (causal && n0 > m0 + BM - 1) {
        // fully masked tile: fill -1e30 and exit
        const float4 mv = make_float4(-1e30f, -1e30f, -1e30f, -1e30f);
        const int col = (tid & 31) * 4, row = tid >> 5;
        #pragma unroll
        for (int r = 0; r < 16; r++)
            *(float4*)(C + coff + (long)(m0 + row + r * 8) * ldc + n0 + col) = mv;
        return;
    }

    __shared__ __align__(16) unsigned As[2][BM * 20];
    __shared__ __align__(16) unsigned Bs[2][BK * BNP];

    const int arow = tid >> 2, acol = (tid & 3) * 4;
    int brow, bcol;
    if (BN == 128) { brow = tid >> 5; bcol = (tid & 31) * 4; }
    else           { brow = tid >> 4; bcol = (tid & 15) * 4; }

    const float* Ap = A + (long)(m0 + arow) * lda + acol;
    const float* Bp = B + (long)brow * ldb + n0 + bcol;

    const int wid = tid >> 5, lane = tid & 31;
    const int wm = wid & 3, wn = wid >> 2;
    const int grp = lane >> 2, qd = lane & 3;

    float acc[2][NTN][4];
    #pragma unroll
    for (int i = 0; i < 2; i++)
        #pragma unroll
        for (int j = 0; j < NTN; j++)
            #pragma unroll
            for (int l = 0; l < 4; l++) acc[i][j][l] = 0.f;

    const int nit = K / BK;

    float4 ra0, ra1, rb0, rb1;
    // prologue: tile 0
    ra0 = *(const float4*)Ap;
    ra1 = *(const float4*)(Ap + 64 * lda);
    rb0 = *(const float4*)Bp;
    if (BN == 128) rb1 = *(const float4*)(Bp + 8 * ldb);
    *(uint4*)&As[0][arow * 20 + acol] =
        make_uint4(f2tf(ra0.x), f2tf(ra0.y), f2tf(ra0.z), f2tf(ra0.w));
    *(uint4*)&As[0][(arow + 64) * 20 + acol] =
        make_uint4(f2tf(ra1.x), f2tf(ra1.y), f2tf(ra1.z), f2tf(ra1.w));
    *(uint4*)&Bs[0][brow * BNP + bcol] =
        make_uint4(f2tf(rb0.x), f2tf(rb0.y), f2tf(rb0.z), f2tf(rb0.w));
    if (BN == 128)
        *(uint4*)&Bs[0][(brow + 8) * BNP + bcol] =
            make_uint4(f2tf(rb1.x), f2tf(rb1.y), f2tf(rb1.z), f2tf(rb1.w));
    __syncthreads();

    for (int it = 0; it < nit; it++) {
        const int cur = it & 1;
        const bool more = (it + 1 < nit);
        if (more) {
            const float* Ap2 = Ap + (it + 1) * BK;
            const float* Bp2 = Bp + (long)(it + 1) * BK * ldb;
            ra0 = *(const float4*)Ap2;
            ra1 = *(const float4*)(Ap2 + 64 * lda);
            rb0 = *(const float4*)Bp2;
            if (BN == 128) rb1 = *(const float4*)(Bp2 + 8 * ldb);
        }

        const unsigned* as = As[cur];
        const unsigned* bs = Bs[cur];
        #pragma unroll
        for (int ks = 0; ks < 2; ks++) {
            unsigned af[2][4];
            #pragma unroll
            for (int mt = 0; mt < 2; mt++) {
                const int r = wm * 32 + mt * 16 + grp;
                af[mt][0] = as[r * 20 + ks * 8 + qd];
                af[mt][1] = as[(r + 8) * 20 + ks * 8 + qd];
                af[mt][2] = as[r * 20 + ks * 8 + qd + 4];
                af[mt][3] = as[(r + 8) * 20 + ks * 8 + qd + 4];
            }
            #pragma unroll
            for (int nt = 0; nt < NTN; nt++) {
                const int cN = wn * WN + nt * 8 + grp;
                const unsigned b0 = bs[(ks * 8 + qd) * BNP + cN];
                const unsigned b1 = bs[(ks * 8 + qd + 4) * BNP + cN];
                mma8(acc[0][nt], af[0], b0, b1);
                mma8(acc[1][nt], af[1], b0, b1);
            }
        }

        if (more) {
            const int nxt = cur ^ 1;
            *(uint4*)&As[nxt][arow * 20 + acol] =
                make_uint4(f2tf(ra0.x), f2tf(ra0.y), f2tf(ra0.z), f2tf(ra0.w));
            *(uint4*)&As[nxt][(arow + 64) * 20 + acol] =
                make_uint4(f2tf(ra1.x), f2tf(ra1.y), f2tf(ra1.z), f2tf(ra1.w));
            *(uint4*)&Bs[nxt][brow * BNP + bcol] =
                make_uint4(f2tf(rb0.x), f2tf(rb0.y), f2tf(rb0.z), f2tf(rb0.w));
            if (BN == 128)
                *(uint4*)&Bs[nxt][(brow + 8) * BNP + bcol] =
                    make_uint4(f2tf(rb1.x), f2tf(rb1.y), f2tf(rb1.z), f2tf(rb1.w));
        }
        __syncthreads();
    }

    // epilogue
    const bool dob = flags & 1, dores = flags & 2, dorelu = flags & 4;
    #pragma unroll
    for (int mt = 0; mt < 2; mt++) {
        #pragma unroll
        for (int nt = 0; nt < NTN; nt++) {
            const int r = m0 + wm * 32 + mt * 16 + grp;
            const int c = n0 + wn * WN + nt * 8 + qd * 2;
            #pragma unroll
            for (int half = 0; half < 2; half++) {
                const int rr = r + half * 8;
                float v0 = acc[mt][nt][half * 2 + 0];
                float v1 = acc[mt][nt][half * 2 + 1];
                if (dob) { v0 += bias[c]; v1 += bias[c + 1]; }
                if (dores) {
                    const float* rp = Res + coff + (long)rr * ldc + c;
                    v0 += rp[0]; v1 += rp[1];
                }
                if (dorelu) { v0 = fmaxf(v0, 0.f); v1 = fmaxf(v1, 0.f); }
                if (causal) {
                    v0 = (c     <= rr) ? v0 * scale : -1e30f;
                    v1 = (c + 1 <= rr) ? v1 * scale : -1e30f;
                }
                *(float2*)(C + coff + (long)rr * ldc + c) = make_float2(v0, v1);
            }
        }
    }
}

// ---------------------------------------------------------------------------
// Fused QKV: one GEMM M=2048, N=1024(=H*DH), K=1024 per z in {q,k,v}.
// Weight is [H][DM][DH]; B(k,n) = W[(n>>6)*DM + k][n&63].
// ---------------------------------------------------------------------------
__global__ void __launch_bounds__(256)
gemm_qkv(const float* __restrict__ X,
         const float* __restrict__ Wq, const float* __restrict__ Wk,
         const float* __restrict__ Wv,
         float* __restrict__ Q, float* __restrict__ Ko, float* __restrict__ V)
{
    constexpr int BM = 128, BN = 128, BK = 16;
    constexpr int WN = 64, NTN = 8, BNP = BN + 8;

    const float* W = (blockIdx.z == 0) ? Wq : (blockIdx.z == 1) ? Wk : Wv;
    float* C = (blockIdx.z == 0) ? Q : (blockIdx.z == 1) ? Ko : V;

    const int m0 = blockIdx.x * BM;
    const int n0 = blockIdx.y * BN;
    const int tid = threadIdx.x;

    __shared__ __align__(16) unsigned As[2][BM * 20];
    __shared__ __align__(16) unsigned Bs[2][BK * BNP];

    const int arow = tid >> 2, acol = (tid & 3) * 4;
    const int brow = tid >> 5, bcol = (tid & 31) * 4;

    const float* Ap = X + (long)(m0 + arow) * DM + acol;
    const int gn = n0 + bcol;
    const float* Bp = W + ((long)(gn >> 6) * DM + brow) * DH + (gn & 63);

    const int wid = tid >> 5, lane = tid & 31;
    const int wm = wid & 3, wn = wid >> 2;
    const int grp = lane >> 2, qd = lane & 3;

    float acc[2][NTN][4];
    #pragma unroll
    for (int i = 0; i < 2; i++)
        #pragma unroll
        for (int j = 0; j < NTN; j++)
            #pragma unroll
            for (int l = 0; l < 4; l++) acc[i][j][l] = 0.f;

    const int nit = DM / BK;

    float4 ra0, ra1, rb0, rb1;
    ra0 = *(const float4*)Ap;
    ra1 = *(const float4*)(Ap + 64 * DM);
    rb0 = *(const float4*)Bp;
    rb1 = *(const float4*)(Bp + 8 * DH);
    *(uint4*)&As[0][arow * 20 + acol] =
        make_uint4(f2tf(ra0.x), f2tf(ra0.y), f2tf(ra0.z), f2tf(ra0.w));
    *(uint4*)&As[0][(arow + 64) * 20 + acol] =
        make_uint4(f2tf(ra1.x), f2tf(ra1.y), f2tf(ra1.z), f2tf(ra1.w));
    *(uint4*)&Bs[0][brow * BNP + bcol] =
        make_uint4(f2tf(rb0.x), f2tf(rb0.y), f2tf(rb0.z), f2tf(rb0.w));
    *(uint4*)&Bs[0][(brow + 8) * BNP + bcol] =
        make_uint4(f2tf(rb1.x), f2tf(rb1.y), f2tf(rb1.z), f2tf(rb1.w));
    __syncthreads();

    for (int it = 0; it < nit; it++) {
        const int cur = it & 1;
        const bool more = (it + 1 < nit);
        if (more) {
            const float* Ap2 = Ap + (it + 1) * BK;
            const float* Bp2 = Bp + (long)(it + 1) * BK * DH;
            ra0 = *(const float4*)Ap2;
            ra1 = *(const float4*)(Ap2 + 64 * DM);
            rb0 = *(const float4*)Bp2;
            rb1 = *(const float4*)(Bp2 + 8 * DH);
        }

        const unsigned* as = As[cur];
        const unsigned* bs = Bs[cur];
        #pragma unroll
        for (int ks = 0; ks < 2; ks++) {
            unsigned af[2][4];
            #pragma unroll
            for (int mt = 0; mt < 2; mt++) {
                const int r = wm * 32 + mt * 16 + grp;
                af[mt][0] = as[r * 20 + ks * 8 + qd];
                af[mt][1] = as[(r + 8) * 20 + ks * 8 + qd];
                af[mt][2] = as[r * 20 + ks * 8 + qd + 4];
                af[mt][3] = as[(r + 8) * 20 + ks * 8 + qd + 4];
            }
            #pragma unroll
            for (int nt = 0; nt < NTN; nt++) {
                const int cN = wn * WN + nt * 8 + grp;
                const unsigned b0 = bs[(ks * 8 + qd) * BNP + cN];
                const unsigned b1 = bs[(ks * 8 + qd + 4) * BNP + cN];
                mma8(acc[0][nt], af[0], b0, b1);
                mma8(acc[1][nt], af[1], b0, b1);
            }
        }

        if (more) {
            const int nxt = cur ^ 1;
            *(uint4*)&As[nxt][arow * 20 + acol] =
                make_uint4(f2tf(ra0.x), f2tf(ra0.y), f2tf(ra0.z), f2tf(ra0.w));
            *(uint4*)&As[nxt][(arow + 64) * 20 + acol] =
                make_uint4(f2tf(ra1.x), f2tf(ra1.y), f2tf(ra1.z), f2tf(ra1.w));
            *(uint4*)&Bs[nxt][brow * BNP + bcol] =
                make_uint4(f2tf(rb0.x), f2tf(rb0.y), f2tf(rb0.z), f2tf(rb0.w));
            *(uint4*)&Bs[nxt][(brow + 8) * BNP + bcol] =
                make_uint4(f2tf(rb1.x), f2tf(rb1.y), f2tf(rb1.z), f2tf(rb1.w));
        }
        __syncthreads();
    }

    #pragma unroll
    for (int mt = 0; mt < 2; mt++) {
        #pragma unroll
        for (int nt = 0; nt < NTN; nt++) {
            const int r = m0 + wm * 32 + mt * 16 + grp;
            const int c = n0 + wn * WN + nt * 8 + qd * 2;
            #pragma unroll
            for (int half = 0; half < 2; half++) {
                const int rr = r + half * 8;
                *(float2*)(C + (long)rr * DM + c) =
                    make_float2(acc[mt][nt][half * 2], acc[mt][nt][half * 2 + 1]);
            }
        }
    }
}

// ---------------------------------------------------------------------------
// Transpose K per head: kt[(b*NH+h)*DH + c][j] = k[b*NS+j][h*DH+c]
// ---------------------------------------------------------------------------
__global__ void __launch_bounds__(256)
transpose_k(const float* __restrict__ k, float* __restrict__ kt)
{
    const int z = blockIdx.z;
    const int b = z >> 4, h = z & 15;
    const int j0 = blockIdx.x * 32, c0 = blockIdx.y * 32;
    __shared__ float t[32][33];
    const int tx = threadIdx.x & 31, ty = threadIdx.x >> 5;
    #pragma unroll
    for (int r = 0; r < 32; r += 8)
        t[ty + r][tx] = k[(long)(b * NS + j0 + ty + r) * DM + h * DH + c0 + tx];
    __syncthreads();
    #pragma unroll
    for (int r = 0; r < 32; r += 8)
        kt[((long)z * DH + c0 + ty + r) * NS + j0 + tx] = t[tx][ty + r];
}

// ---------------------------------------------------------------------------
// Row softmax over 1024 cols
// ---------------------------------------------------------------------------
__global__ void __launch_bounds__(256)
softmax_kernel(float* __restrict__ sc)
{
    float* p = sc + (long)blockIdx.x * NS;
    const int tid = threadIdx.x;
    __shared__ float red[256];

    float vals[4];
    float lm = -1e30f;
    #pragma unroll
    for (int i = 0; i < 4; i++) { vals[i] = p[tid + i * 256]; lm = fmaxf(lm, vals[i]); }
    red[tid] = lm; __syncthreads();
    for (int s = 128; s > 0; s >>= 1) {
        if (tid < s) red[tid] = fmaxf(red[tid], red[tid + s]);
        __syncthreads();
    }
    const float mx = red[0]; __syncthreads();

    float ls = 0.0f;
    #pragma unroll
    for (int i = 0; i < 4; i++) { vals[i] = expf(vals[i] - mx); ls += vals[i]; }
    red[tid] = ls; __syncthreads();
    for (int s = 128; s > 0; s >>= 1) {
        if (tid < s) red[tid] += red[tid + s];
        __syncthreads();
    }
    const float inv = 1.0f / red[0];
    #pragma unroll
    for (int i = 0; i < 4; i++) p[tid + i * 256] = vals[i] * inv;
}

// ---------------------------------------------------------------------------
// LayerNorm (unbiased std, divide by (std + eps))
// ---------------------------------------------------------------------------
__global__ void __launch_bounds__(256)
ln_kernel(const float* __restrict__ in, const float* __restrict__ g,
          const float* __restrict__ b, float* __restrict__ out)
{
    const float* p = in + (long)blockIdx.x * DM;
    float* po = out + (long)blockIdx.x * DM;
    const int tid = threadIdx.x;
    __shared__ float red[256];

    float vals[4];
    float s = 0.0f;
    #pragma unroll
    for (int i = 0; i < 4; i++) { vals[i] = p[tid + i * 256]; s += vals[i]; }
    red[tid] = s; __syncthreads();
    for (int st = 128; st > 0; st >>= 1) {
        if (tid < st) red[tid] += red[tid + st];
        __syncthreads();
    }
    const float mean = red[0] * (1.0f / DM); __syncthreads();

    float sq = 0.0f;
    #pragma unroll
    for (int i = 0; i < 4; i++) { float d = vals[i] - mean; sq += d * d; }
    red[tid] = sq; __syncthreads();
    for (int st = 128; st > 0; st >>= 1) {
        if (tid < st) red[tid] += red[tid + st];
        __syncthreads();
    }
    const float sd = sqrtf(red[0] / (DM - 1));
    const float inv = 1.0f / (sd + 1e-6f);
    #pragma unroll
    for (int i = 0; i < 4; i++) {
        const int d = tid + i * 256;
        po[d] = g[d] * (vals[i] - mean) * inv + b[d];
    }
}

// ---------------------------------------------------------------------------
// Embedding + positional encoding
// ---------------------------------------------------------------------------
__global__ void __launch_bounds__(256)
embed_kernel(const int* __restrict__ tokens, const float* __restrict__ emb,
             float* __restrict__ x)
{
    const int t = blockIdx.x;
    const int s = t & (NS - 1);
    const int tok = tokens[t];
    const float* e = emb + (long)tok * DM;
    float* xo = x + (long)t * DM;
    const float nlog = -9.210340371976184f / (float)DM;
    for (int d = threadIdx.x; d < DM; d += 256) {
        const int i2 = d & ~1;
        const float freq = expf((float)i2 * nlog);
        const float ang = (float)s * freq;
        const float pe = (d & 1) ? cosf(ang) : sinf(ang);
        xo[d] = e[d] * 32.0f + pe;
    }
}

// ---------------------------------------------------------------------------
extern "C" void kernel_launch(void* const* d_in, const int* in_sizes, int n_in,
                              void* d_out, int out_size)
{
    const int*   tokens = (const int*)  d_in[0];
    const float* emb    = (const float*)d_in[1];
    const float* Wq     = (const float*)d_in[2];
    const float* Wk     = (const float*)d_in[3];
    const float* Wv     = (const float*)d_in[4];
    const float* Wo     = (const float*)d_in[5];
    const float* bo     = (const float*)d_in[6];
    const float* ln1g   = (const float*)d_in[7];
    const float* ln1b   = (const float*)d_in[8];
    const float* W1     = (const float*)d_in[9];
    const float* b1     = (const float*)d_in[10];
    const float* W2     = (const float*)d_in[11];
    const float* b2     = (const float*)d_in[12];
    const float* ln2g   = (const float*)d_in[13];
    const float* ln2b   = (const float*)d_in[14];
    const float* Wout   = (const float*)d_in[15];
    const float* bout   = (const float*)d_in[16];
    float* out = (float*)d_out;

    float *x, *res, *q, *k, *v, *o, *ffn, *kt, *sc;
    cudaGetSymbolAddress((void**)&x,   g_x);
    cudaGetSymbolAddress((void**)&res, g_res);
    cudaGetSymbolAddress((void**)&q,   g_q);
    cudaGetSymbolAddress((void**)&k,   g_k);
    cudaGetSymbolAddress((void**)&v,   g_v);
    cudaGetSymbolAddress((void**)&o,   g_o);
    cudaGetSymbolAddress((void**)&ffn, g_ffn);
    cudaGetSymbolAddress((void**)&kt,  g_kt);
    cudaGetSymbolAddress((void**)&sc,  g_sc);

    embed_kernel<<<NT, 256>>>(tokens, emb, x);

    for (int l = 0; l < NL; l++) {
        const float* Wql = Wq + (long)l * NH * DM * DH;
        const float* Wkl = Wk + (long)l * NH * DM * DH;
        const float* Wvl = Wv + (long)l * NH * DM * DH;
        const float* Wol = Wo + (long)l * DM * DM;
        const float* bol = bo + (long)l * DM;
        const float* W1l = W1 + (long)l * DM * DFF;
        const float* b1l = b1 + (long)l * DFF;
        const float* W2l = W2 + (long)l * DFF * DM;
        const float* b2l = b2 + (long)l * DM;

        // fused QKV: grid.z selects q/k/v
        gemm_qkv<<<dim3(NT / 128, DM / 128, 3), 256>>>(x, Wql, Wkl, Wvl, q, k, v);

        // K transpose per head
        transpose_k<<<dim3(NS / 32, DH / 32, NB * NH), 256>>>(k, kt);

        // scores = Q @ K^T / 8, causal
        gemm_tc<128><<<dim3(NS / 128, NS / 128, NB * NH), 256>>>(
            q, kt, nullptr, nullptr, sc, DH,
            DM, NS, NS, NH,
            (long)NS * DM, 64, (long)NH * DH * NS, (long)DH * NS,
            (long)NH * NS * NS, (long)NS * NS,
            8, 0.125f);

        softmax_kernel<<<NB * NH * NS, 256>>>(sc);

        // o = att @ V  (N = 64 per head)
        gemm_tc<64><<<dim3(NS / 128, 1, NB * NH), 256>>>(
            sc, v, nullptr, nullptr, o, NS,
            NS, DM, DM, NH,
            (long)NH * NS * NS, (long)NS * NS, (long)NS * DM, 64,
            (long)NS * DM, 64,
            0, 1.f);

        // O projection + bias + residual
        gemm_tc<128><<<dim3(NT / 128, DM / 128), 256>>>(
            o, Wol, bol, x, res, DM,
            DM, DM, DM, 1, 0, 0, 0, 0, 0, 0,
            1 | 2, 1.f);
        ln_kernel<<<NT, 256>>>(res, ln1g + (long)l * DM, ln1b + (long)l * DM, x);

        // FFN
        gemm_tc<128><<<dim3(NT / 128, DFF / 128), 256>>>(
            x, W1l, b1l, nullptr, ffn, DM,
            DM, DFF, DFF, 1, 0, 0, 0, 0, 0, 0,
            1 | 4, 1.f);
        gemm_tc<128><<<dim3(NT / 128, DM / 128), 256>>>(
            ffn, W2l, b2l, x, res, DFF,
            DFF, DM, DM, 1, 0, 0, 0, 0, 0, 0,
            1 | 2, 1.f);
        ln_kernel<<<NT, 256>>>(res, ln2g + (long)l * DM, ln2b + (long)l * DM, x);
    }

    gemm_tc<128><<<dim3(NT / 128, NV / 128), 256>>>(
        x, Wout, bout, nullptr, out, DM,
        DM, NV, NV, 1, 0, 0, 0, 0, 0, 0,
        1, 1.f);
}